// round 1
// baseline (speedup 1.0000x reference)
#include <cuda_runtime.h>
#include <math.h>

#define L_LAYERS 4
#define BATCH    8
#define PHN      24
#define PWN      24
#define PATCHES  576
#define DIM      1024
#define NRL      12      // 3 radii * 4 layers
#define NPAIRS   28      // unordered batch pairs
#define OUTH     336
#define OUTW     336

// ---------------- device scratch (static; no allocations allowed) -----------
__device__ float    g_featn[(size_t)NRL * BATCH * PATCHES * DIM];     // ~226.5 MB
__device__ unsigned g_keys[NRL * BATCH * PATCHES * BATCH];            // 442368
__device__ float    g_scores[BATCH * PATCHES];

// monotone float<->uint mapping so atomicMax(uint) == float max
__device__ __forceinline__ unsigned enc_f(float x) {
    unsigned u = __float_as_uint(x);
    return (u & 0x80000000u) ? ~u : (u | 0x80000000u);
}
__device__ __forceinline__ float dec_f(unsigned k) {
    unsigned u = (k & 0x80000000u) ? (k & 0x7FFFFFFFu) : ~k;
    return __uint_as_float(u);
}

// ---------------- init ------------------------------------------------------
__global__ void init_keys_kernel() {
    int i = blockIdx.x * 256 + threadIdx.x;
    if (i < NRL * BATCH * PATCHES * BATCH) g_keys[i] = 0u;  // decodes below any real dot
}

// ---------------- pool (zero-pad avg, /r^2) + L2 normalize ------------------
// grid: (PATCHES, BATCH, NRL), block: 256 threads (each owns 4 dims)
__global__ void pool_norm_kernel(const float* __restrict__ feat) {
    int p = blockIdx.x, b = blockIdx.y, z = blockIdx.z;
    int rIdx = z >> 2;                  // 0,1,2
    int l    = z & 3;
    int r    = 1 + 2 * rIdx;            // 1,3,5
    int ph = p / PWN, pw = p % PWN;
    int t  = threadIdx.x;
    int d0 = t * 4;

    const float* base = feat + ((size_t)(l * BATCH + b) * PATCHES) * DIM;

    float4 s = make_float4(0.f, 0.f, 0.f, 0.f);
    int pad = r >> 1;
    for (int dy = -pad; dy <= pad; ++dy) {
        int y = ph + dy;
        if ((unsigned)y >= (unsigned)PHN) continue;
        for (int dx = -pad; dx <= pad; ++dx) {
            int x = pw + dx;
            if ((unsigned)x >= (unsigned)PWN) continue;
            const float4 v = *(const float4*)(base + (size_t)(y * PWN + x) * DIM + d0);
            s.x += v.x; s.y += v.y; s.z += v.z; s.w += v.w;
        }
    }
    float inv = 1.0f / (float)(r * r);
    s.x *= inv; s.y *= inv; s.z *= inv; s.w *= inv;

    float sq = s.x * s.x + s.y * s.y + s.z * s.z + s.w * s.w;
    #pragma unroll
    for (int o = 16; o > 0; o >>= 1) sq += __shfl_xor_sync(0xffffffffu, sq, o);

    __shared__ float warpsum[8];
    __shared__ float s_rnorm;
    if ((t & 31) == 0) warpsum[t >> 5] = sq;
    __syncthreads();
    if (t == 0) {
        float x = 0.f;
        #pragma unroll
        for (int w = 0; w < 8; ++w) x += warpsum[w];
        s_rnorm = rsqrtf(x);
    }
    __syncthreads();
    float rn = s_rnorm;

    float4 o4 = make_float4(s.x * rn, s.y * rn, s.z * rn, s.w * rn);
    *(float4*)(g_featn + ((size_t)(z * BATCH + b) * PATCHES + p) * DIM + d0) = o4;
}

// ---------------- fused GEMM + bidirectional max reduction ------------------
// For batch pair (b<c): D = A_b @ A_c^T over D=1024; rowmax -> dotmax[b,p,c],
// colmax -> dotmax[c,q,b]. Tile 64x64x16, 256 threads, 4x4 microtiles.
// grid: (81 tiles, 28 pairs, 12 rl)
__global__ void __launch_bounds__(256) gemm_max_kernel() {
    int tile = blockIdx.x;
    int ti = tile / 9, tj = tile % 9;
    int pair = blockIdx.y;
    int rl = blockIdx.z;

    // decode unordered pair index -> (b, c) with b < c
    int b = 0, rem = pair;
    #pragma unroll
    for (int bb = 0; bb < 7; ++bb) {
        int cnt = 7 - bb;
        if (rem < cnt) { b = bb; break; }
        rem -= cnt;
    }
    int c = b + 1 + rem;

    const float* A  = g_featn + ((size_t)(rl * BATCH + b) * PATCHES + ti * 64) * DIM;
    const float* Bm = g_featn + ((size_t)(rl * BATCH + c) * PATCHES + tj * 64) * DIM;

    __shared__ float As[16][64];
    __shared__ float Bs[16][64];

    int t  = threadIdx.x;
    int tx = t & 15;        // column group
    int ty = t >> 4;        // row group
    int lrow = t >> 2;      // 0..63: row this thread loads
    int lk4  = (t & 3) * 4; // k-offset within 16-wide slab

    const float* Ag = A  + (size_t)lrow * DIM + lk4;
    const float* Bg = Bm + (size_t)lrow * DIM + lk4;

    float acc[4][4] = {};

    float4 va = *(const float4*)(Ag);
    float4 vb = *(const float4*)(Bg);

    for (int kt = 0; kt < 64; ++kt) {
        As[lk4 + 0][lrow] = va.x; As[lk4 + 1][lrow] = va.y;
        As[lk4 + 2][lrow] = va.z; As[lk4 + 3][lrow] = va.w;
        Bs[lk4 + 0][lrow] = vb.x; Bs[lk4 + 1][lrow] = vb.y;
        Bs[lk4 + 2][lrow] = vb.z; Bs[lk4 + 3][lrow] = vb.w;
        __syncthreads();

        if (kt < 63) {   // prefetch next slab while computing
            va = *(const float4*)(Ag + (kt + 1) * 16);
            vb = *(const float4*)(Bg + (kt + 1) * 16);
        }

        #pragma unroll
        for (int k = 0; k < 16; ++k) {
            float4 a  = *(const float4*)&As[k][ty * 4];
            float4 bv = *(const float4*)&Bs[k][tx * 4];
            acc[0][0] += a.x * bv.x; acc[0][1] += a.x * bv.y;
            acc[0][2] += a.x * bv.z; acc[0][3] += a.x * bv.w;
            acc[1][0] += a.y * bv.x; acc[1][1] += a.y * bv.y;
            acc[1][2] += a.y * bv.z; acc[1][3] += a.y * bv.w;
            acc[2][0] += a.z * bv.x; acc[2][1] += a.z * bv.y;
            acc[2][2] += a.z * bv.z; acc[2][3] += a.z * bv.w;
            acc[3][0] += a.w * bv.x; acc[3][1] += a.w * bv.y;
            acc[3][2] += a.w * bv.z; acc[3][3] += a.w * bv.w;
        }
        __syncthreads();
    }

    __shared__ float red[64][17];

    // row-wise max (over this 64-col slab) -> dotmax[rl, b, row, c]
    #pragma unroll
    for (int i = 0; i < 4; ++i) {
        float m = fmaxf(fmaxf(acc[i][0], acc[i][1]), fmaxf(acc[i][2], acc[i][3]));
        red[ty * 4 + i][tx] = m;
    }
    __syncthreads();
    if (t < 64) {
        float m = red[t][0];
        #pragma unroll
        for (int j = 1; j < 16; ++j) m = fmaxf(m, red[t][j]);
        unsigned* dst = &g_keys[((size_t)(rl * BATCH + b) * PATCHES + (size_t)ti * 64 + t) * BATCH + c];
        atomicMax(dst, enc_f(m));
    }
    __syncthreads();

    // column-wise max -> dotmax[rl, c, col, b]
    #pragma unroll
    for (int j = 0; j < 4; ++j) {
        float m = fmaxf(fmaxf(acc[0][j], acc[1][j]), fmaxf(acc[2][j], acc[3][j]));
        red[tx * 4 + j][ty] = m;
    }
    __syncthreads();
    if (t < 64) {
        float m = red[t][0];
        #pragma unroll
        for (int j = 1; j < 16; ++j) m = fmaxf(m, red[t][j]);
        unsigned* dst = &g_keys[((size_t)(rl * BATCH + c) * PATCHES + (size_t)tj * 64 + t) * BATCH + b];
        atomicMax(dst, enc_f(m));
    }
}

// ---------------- per-(b,p) score: mean over rl of mean(top-2 smallest d) ---
__global__ void score_kernel() {
    int idx = blockIdx.x * 256 + threadIdx.x;
    if (idx >= BATCH * PATCHES) return;
    int b = idx / PATCHES;
    int p = idx % PATCHES;

    float sum = 0.f;
    #pragma unroll
    for (int rl = 0; rl < NRL; ++rl) {
        const unsigned* k = &g_keys[((size_t)(rl * BATCH + b) * PATCHES + p) * BATCH];
        float d1 = 1e30f, d2 = 1e30f;
        #pragma unroll
        for (int cc = 0; cc < BATCH; ++cc) {
            if (cc == b) continue;
            float dot = dec_f(k[cc]);
            float d = sqrtf(fmaxf(2.0f - 2.0f * dot, 0.0f));
            if (d < d1) { d2 = d1; d1 = d; }
            else if (d < d2) { d2 = d; }
        }
        sum += 0.5f * (d1 + d2);
    }
    g_scores[idx] = sum * (1.0f / 12.0f);
}

// ---------------- scores_image: max over patches ----------------------------
__global__ void image_kernel(float* __restrict__ out) {
    int b = blockIdx.x;
    int t = threadIdx.x;
    float m = -1e30f;
    for (int p = t; p < PATCHES; p += 256) m = fmaxf(m, g_scores[b * PATCHES + p]);
    #pragma unroll
    for (int o = 16; o > 0; o >>= 1) m = fmaxf(m, __shfl_xor_sync(0xffffffffu, m, o));
    __shared__ float ws[8];
    if ((t & 31) == 0) ws[t >> 5] = m;
    __syncthreads();
    if (t == 0) {
        float mm = ws[0];
        #pragma unroll
        for (int w = 1; w < 8; ++w) mm = fmaxf(mm, ws[w]);
        out[b] = mm;
    }
}

// ---------------- bilinear 24->336 (align_corners) --------------------------
__global__ void bilinear_kernel(float* __restrict__ out) {
    int idx = blockIdx.x * 256 + threadIdx.x;
    if (idx >= BATCH * OUTH * OUTW) return;
    int b  = idx / (OUTH * OUTW);
    int rr = idx % (OUTH * OUTW);
    int y = rr / OUTW, x = rr % OUTW;

    const float sc = 23.0f / 335.0f;
    float fy = (float)y * sc;
    float fx = (float)x * sc;
    int y0 = (int)floorf(fy); int y1 = min(y0 + 1, PHN - 1);
    int x0 = (int)floorf(fx); int x1 = min(x0 + 1, PWN - 1);
    float wy = fy - (float)y0;
    float wx = fx - (float)x0;

    const float* s = g_scores + b * PATCHES;
    float f00 = s[y0 * PWN + x0];
    float f01 = s[y0 * PWN + x1];
    float f10 = s[y1 * PWN + x0];
    float f11 = s[y1 * PWN + x1];

    out[BATCH + idx] = f00 * (1.f - wy) * (1.f - wx) + f01 * (1.f - wy) * wx
                     + f10 * wy * (1.f - wx)         + f11 * wy * wx;
}

// ---------------- launch ----------------------------------------------------
extern "C" void kernel_launch(void* const* d_in, const int* in_sizes, int n_in,
                              void* d_out, int out_size) {
    const float* feat = (const float*)d_in[0];
    float* out = (float*)d_out;

    init_keys_kernel<<<(NRL * BATCH * PATCHES * BATCH + 255) / 256, 256>>>();
    pool_norm_kernel<<<dim3(PATCHES, BATCH, NRL), 256>>>(feat);
    gemm_max_kernel<<<dim3(81, NPAIRS, NRL), 256>>>();
    score_kernel<<<(BATCH * PATCHES + 255) / 256, 256>>>();
    image_kernel<<<BATCH, 256>>>(out);
    bilinear_kernel<<<(BATCH * OUTH * OUTW + 255) / 256, 256>>>(out);
}

// round 3
// speedup vs baseline: 6.3640x; 6.3640x over previous
#include <cuda_runtime.h>
#include <cuda_bf16.h>
#include <cstdint>
#include <math.h>

#define L_LAYERS 4
#define BATCH    8
#define PHN      24
#define PWN      24
#define PATCHES  576
#define DIM      1024
#define NRL      12
#define NPAIRS   28
#define OUTH     336
#define OUTW     336
#define PADP     640            // 5 tiles of 128
#define TILE     128
#define KS       32             // k per slab
#define NSLAB    32             // 1024/32
#define STAGES   3
#define ROWB     80             // smem row stride bytes (64 data + 16 pad)
#define STAGEB   (2 * TILE * ROWB)   // A+B per stage = 20480
#define SMEM_DYN (STAGES * STAGEB)   // 61440

// ---------------- device scratch ----------------
__device__ __align__(16) __nv_bfloat16 g_featn[(size_t)NRL * BATCH * PADP * DIM];
__device__ unsigned g_keys[NRL * BATCH * PADP * BATCH];
__device__ float    g_scores[BATCH * PATCHES];

__device__ __forceinline__ unsigned enc_f(float x) {
    unsigned u = __float_as_uint(x);
    return (u & 0x80000000u) ? ~u : (u | 0x80000000u);
}
__device__ __forceinline__ float dec_f(unsigned k) {
    unsigned u = (k & 0x80000000u) ? (k & 0x7FFFFFFFu) : ~k;
    return __uint_as_float(u);
}

__device__ __forceinline__ uint32_t smem_u32(const void* p) {
    uint32_t a;
    asm("{ .reg .u64 t; cvta.to.shared.u64 t, %1; cvt.u32.u64 %0, t; }" : "=r"(a) : "l"(p));
    return a;
}

#define CP16(dst, src) asm volatile("cp.async.cg.shared.global [%0], [%1], 16;" :: "r"(dst), "l"(src) : "memory")
#define CP_COMMIT()    asm volatile("cp.async.commit_group;" ::: "memory")

#define LDSM_X4(r0, r1, r2, r3, a) \
    asm volatile("ldmatrix.sync.aligned.m8n8.x4.shared.b16 {%0,%1,%2,%3}, [%4];" \
        : "=r"(r0), "=r"(r1), "=r"(r2), "=r"(r3) : "r"(a))

#define MMA16816(c, a, b) \
    asm volatile("mma.sync.aligned.m16n8k16.row.col.f32.bf16.bf16.f32 " \
        "{%0,%1,%2,%3}, {%4,%5,%6,%7}, {%8,%9}, {%0,%1,%2,%3};" \
        : "+f"((c)[0]), "+f"((c)[1]), "+f"((c)[2]), "+f"((c)[3]) \
        : "r"((a)[0]), "r"((a)[1]), "r"((a)[2]), "r"((a)[3]), "r"((b)[0]), "r"((b)[1]))

// ---------------- init / pad ----------------
__global__ void init_keys_kernel() {
    int i = blockIdx.x * 256 + threadIdx.x;
    if (i < NRL * BATCH * PADP * BATCH) g_keys[i] = 0u;
}
__global__ void zero_pad_kernel() {
    int i = blockIdx.x * 256 + threadIdx.x;
    const int ROWV = DIM / 8;                          // 128 uint4 per row
    const int PER  = (PADP - PATCHES) * ROWV;          // 64*128 per slice
    if (i >= NRL * BATCH * PER) return;
    int zb = i / PER, rem = i % PER;
    int row = PATCHES + rem / ROWV, v = rem % ROWV;
    uint4* dst = (uint4*)g_featn;
    dst[((size_t)zb * PADP + row) * ROWV + v] = make_uint4(0, 0, 0, 0);
}

// ---------------- pool + normalize -> bf16 ----------------
__global__ void pool_norm_kernel(const float* __restrict__ feat) {
    int p = blockIdx.x, b = blockIdx.y, z = blockIdx.z;
    int rIdx = z >> 2, l = z & 3;
    int r = 1 + 2 * rIdx;
    int ph = p / PWN, pw = p % PWN;
    int t = threadIdx.x;
    int d0 = t * 4;

    const float* base = feat + ((size_t)(l * BATCH + b) * PATCHES) * DIM;

    float4 s = make_float4(0.f, 0.f, 0.f, 0.f);
    int pad = r >> 1;
    for (int dy = -pad; dy <= pad; ++dy) {
        int y = ph + dy;
        if ((unsigned)y >= (unsigned)PHN) continue;
        for (int dx = -pad; dx <= pad; ++dx) {
            int x = pw + dx;
            if ((unsigned)x >= (unsigned)PWN) continue;
            const float4 v = *(const float4*)(base + (size_t)(y * PWN + x) * DIM + d0);
            s.x += v.x; s.y += v.y; s.z += v.z; s.w += v.w;
        }
    }
    float inv = 1.0f / (float)(r * r);
    s.x *= inv; s.y *= inv; s.z *= inv; s.w *= inv;

    float sq = s.x * s.x + s.y * s.y + s.z * s.z + s.w * s.w;
    #pragma unroll
    for (int o = 16; o > 0; o >>= 1) sq += __shfl_xor_sync(0xffffffffu, sq, o);
    __shared__ float warpsum[8];
    __shared__ float s_rnorm;
    if ((t & 31) == 0) warpsum[t >> 5] = sq;
    __syncthreads();
    if (t == 0) {
        float x = 0.f;
        #pragma unroll
        for (int w = 0; w < 8; ++w) x += warpsum[w];
        s_rnorm = rsqrtf(x);
    }
    __syncthreads();
    float rn = s_rnorm;

    __nv_bfloat162 lo = __floats2bfloat162_rn(s.x * rn, s.y * rn);
    __nv_bfloat162 hi = __floats2bfloat162_rn(s.z * rn, s.w * rn);
    uint2 pk = make_uint2(*(unsigned*)&lo, *(unsigned*)&hi);
    *(uint2*)(g_featn + ((size_t)(z * BATCH + b) * PADP + p) * DIM + d0) = pk;
}

// ---------------- bf16 mma.sync fused GEMM + bidirectional max ----------------
__device__ __forceinline__ void load_slab(uint32_t sA, uint32_t sB,
                                          const char* gA, const char* gB, int t) {
    #pragma unroll
    for (int h = 0; h < 2; ++h) {
        int ch = t + h * 256;           // 0..511
        int r = ch >> 2, c = ch & 3;
        CP16(sA + r * ROWB + c * 16, gA + (size_t)r * (DIM * 2) + c * 16);
        CP16(sB + r * ROWB + c * 16, gB + (size_t)r * (DIM * 2) + c * 16);
    }
}

__global__ void __launch_bounds__(256) gemm_max_mma() {
    extern __shared__ __align__(16) char dsm[];
    uint32_t sbase = smem_u32(dsm);

    int t = threadIdx.x;
    int wid = t >> 5, lane = t & 31;
    int warp_m = wid & 3;               // 4 row groups of 32
    int warp_n = wid >> 2;              // 2 col groups of 64

    int tile = blockIdx.x;
    int ti = tile / 5, tj = tile % 5;
    int pair = blockIdx.y, rl = blockIdx.z;

    int b = 0, rem = pair;
    #pragma unroll
    for (int bb = 0; bb < 7; ++bb) {
        int cnt = 7 - bb;
        if (rem < cnt) { b = bb; break; }
        rem -= cnt;
    }
    int c = b + 1 + rem;

    const char* gA = (const char*)(g_featn + ((size_t)(rl * BATCH + b) * PADP + ti * TILE) * DIM);
    const char* gB = (const char*)(g_featn + ((size_t)(rl * BATCH + c) * PADP + tj * TILE) * DIM);

    float acc[2][8][4];
    #pragma unroll
    for (int mi = 0; mi < 2; ++mi)
        #pragma unroll
        for (int ni = 0; ni < 8; ++ni)
            #pragma unroll
            for (int j = 0; j < 4; ++j) acc[mi][ni][j] = 0.f;

    // per-thread ldmatrix base offsets
    // A: lanes 0-15 rows (lane&15) at kgrp0, lanes 16-31 same rows at k+8
    uint32_t aoff = (uint32_t)((warp_m * 32 + (lane & 15)) * ROWB + ((lane >> 4) * 8) * 2);
    // B: rows n0 + (lane>>4)*8 + (lane&7), kgrp ((lane>>3)&1)
    uint32_t boff = (uint32_t)((warp_n * 64 + (lane >> 4) * 8 + (lane & 7)) * ROWB + (((lane >> 3) & 1) * 8) * 2);

    // prologue: slabs 0, 1
    load_slab(sbase, sbase + TILE * ROWB, gA, gB, t);
    CP_COMMIT();
    load_slab(sbase + STAGEB, sbase + STAGEB + TILE * ROWB, gA + KS * 2, gB + KS * 2, t);
    CP_COMMIT();

    for (int kc = 0; kc < NSLAB; ++kc) {
        if (kc + 2 < NSLAB) {
            int buf = (kc + 2) % STAGES;
            load_slab(sbase + buf * STAGEB, sbase + buf * STAGEB + TILE * ROWB,
                      gA + (size_t)(kc + 2) * (KS * 2), gB + (size_t)(kc + 2) * (KS * 2), t);
            CP_COMMIT();
            asm volatile("cp.async.wait_group 2;" ::: "memory");
        } else if (kc + 2 == NSLAB) {
            asm volatile("cp.async.wait_group 1;" ::: "memory");
        } else {
            asm volatile("cp.async.wait_group 0;" ::: "memory");
        }
        __syncthreads();

        int buf = kc % STAGES;
        uint32_t Ab = sbase + buf * STAGEB;
        uint32_t Bb = Ab + TILE * ROWB;

        #pragma unroll
        for (int ks = 0; ks < 2; ++ks) {
            uint32_t afr[2][4];
            #pragma unroll
            for (int mi = 0; mi < 2; ++mi)
                LDSM_X4(afr[mi][0], afr[mi][1], afr[mi][2], afr[mi][3],
                        Ab + aoff + mi * 16 * ROWB + ks * 32);
            uint32_t bfr[8][2];
            #pragma unroll
            for (int np = 0; np < 4; ++np)
                LDSM_X4(bfr[np * 2][0], bfr[np * 2][1], bfr[np * 2 + 1][0], bfr[np * 2 + 1][1],
                        Bb + boff + np * 16 * ROWB + ks * 32);
            #pragma unroll
            for (int mi = 0; mi < 2; ++mi)
                #pragma unroll
                for (int ni = 0; ni < 8; ++ni)
                    MMA16816(acc[mi][ni], afr[mi], bfr[ni]);
        }
        __syncthreads();
    }

    // ---------------- epilogue: bidirectional max ----------------
    float* rowsmem = (float*)dsm;            // [2][128]
    float* colsmem = rowsmem + 256;          // [4][128]

    // row maxes: thread holds rows r0 = l/4, r0+8 per m-tile
    #pragma unroll
    for (int mi = 0; mi < 2; ++mi) {
        float rm0 = -1e30f, rm1 = -1e30f;
        #pragma unroll
        for (int ni = 0; ni < 8; ++ni) {
            rm0 = fmaxf(rm0, fmaxf(acc[mi][ni][0], acc[mi][ni][1]));
            rm1 = fmaxf(rm1, fmaxf(acc[mi][ni][2], acc[mi][ni][3]));
        }
        #pragma unroll
        for (int o = 1; o < 4; o <<= 1) {
            rm0 = fmaxf(rm0, __shfl_xor_sync(0xffffffffu, rm0, o));
            rm1 = fmaxf(rm1, __shfl_xor_sync(0xffffffffu, rm1, o));
        }
        if ((lane & 3) == 0) {
            int lr = warp_m * 32 + mi * 16 + (lane >> 2);
            rowsmem[warp_n * 128 + lr]     = rm0;
            rowsmem[warp_n * 128 + lr + 8] = rm1;
        }
    }

    // col maxes: thread holds cols ni*8 + (l&3)*2 + {0,1}
    #pragma unroll
    for (int ni = 0; ni < 8; ++ni) {
        float cm0 = fmaxf(fmaxf(acc[0][ni][0], acc[0][ni][2]), fmaxf(acc[1][ni][0], acc[1][ni][2]));
        float cm1 = fmaxf(fmaxf(acc[0][ni][1], acc[0][ni][3]), fmaxf(acc[1][ni][1], acc[1][ni][3]));
        #pragma unroll
        for (int o = 4; o < 32; o <<= 1) {
            cm0 = fmaxf(cm0, __shfl_xor_sync(0xffffffffu, cm0, o));
            cm1 = fmaxf(cm1, __shfl_xor_sync(0xffffffffu, cm1, o));
        }
        if (lane < 4) {
            int lc = warp_n * 64 + ni * 8 + lane * 2;
            colsmem[warp_m * 128 + lc]     = cm0;
            colsmem[warp_m * 128 + lc + 1] = cm1;
        }
    }
    __syncthreads();

    if (t < 128) {
        float m = fmaxf(rowsmem[t], rowsmem[128 + t]);
        int p = ti * TILE + t;
        unsigned* dst = &g_keys[((size_t)(rl * BATCH + b) * PADP + p) * BATCH + c];
        atomicMax(dst, enc_f(m));
    } else {
        int col = t - 128;
        float m = fmaxf(fmaxf(colsmem[col], colsmem[128 + col]),
                        fmaxf(colsmem[256 + col], colsmem[384 + col]));
        int q = tj * TILE + col;
        unsigned* dst = &g_keys[((size_t)(rl * BATCH + c) * PADP + q) * BATCH + b];
        atomicMax(dst, enc_f(m));
    }
}

// ---------------- score / image / bilinear ----------------
__global__ void score_kernel() {
    int idx = blockIdx.x * 256 + threadIdx.x;
    if (idx >= BATCH * PATCHES) return;
    int b = idx / PATCHES;
    int p = idx % PATCHES;

    float sum = 0.f;
    #pragma unroll
    for (int rl = 0; rl < NRL; ++rl) {
        const unsigned* k = &g_keys[((size_t)(rl * BATCH + b) * PADP + p) * BATCH];
        float d1 = 1e30f, d2 = 1e30f;
        #pragma unroll
        for (int cc = 0; cc < BATCH; ++cc) {
            if (cc == b) continue;
            float dot = dec_f(k[cc]);
            float d = sqrtf(fmaxf(2.0f - 2.0f * dot, 0.0f));
            if (d < d1) { d2 = d1; d1 = d; }
            else if (d < d2) { d2 = d; }
        }
        sum += 0.5f * (d1 + d2);
    }
    g_scores[idx] = sum * (1.0f / 12.0f);
}

__global__ void image_kernel(float* __restrict__ out) {
    int b = blockIdx.x;
    int t = threadIdx.x;
    float m = -1e30f;
    for (int p = t; p < PATCHES; p += 256) m = fmaxf(m, g_scores[b * PATCHES + p]);
    #pragma unroll
    for (int o = 16; o > 0; o >>= 1) m = fmaxf(m, __shfl_xor_sync(0xffffffffu, m, o));
    __shared__ float ws[8];
    if ((t & 31) == 0) ws[t >> 5] = m;
    __syncthreads();
    if (t == 0) {
        float mm = ws[0];
        #pragma unroll
        for (int w = 1; w < 8; ++w) mm = fmaxf(mm, ws[w]);
        out[b] = mm;
    }
}

__global__ void bilinear_kernel(float* __restrict__ out) {
    int idx = blockIdx.x * 256 + threadIdx.x;
    if (idx >= BATCH * OUTH * OUTW) return;
    int b = idx / (OUTH * OUTW);
    int rr = idx % (OUTH * OUTW);
    int y = rr / OUTW, x = rr % OUTW;

    const float sc = 23.0f / 335.0f;
    float fy = (float)y * sc;
    float fx = (float)x * sc;
    int y0 = (int)floorf(fy); int y1 = min(y0 + 1, PHN - 1);
    int x0 = (int)floorf(fx); int x1 = min(x0 + 1, PWN - 1);
    float wy = fy - (float)y0;
    float wx = fx - (float)x0;

    const float* s = g_scores + b * PATCHES;
    float f00 = s[y0 * PWN + x0];
    float f01 = s[y0 * PWN + x1];
    float f10 = s[y1 * PWN + x0];
    float f11 = s[y1 * PWN + x1];

    out[BATCH + idx] = f00 * (1.f - wy) * (1.f - wx) + f01 * (1.f - wy) * wx
                     + f10 * wy * (1.f - wx)         + f11 * wy * wx;
}

// ---------------- launch ----------------
extern "C" void kernel_launch(void* const* d_in, const int* in_sizes, int n_in,
                              void* d_out, int out_size) {
    const float* feat = (const float*)d_in[0];
    float* out = (float*)d_out;

    cudaFuncSetAttribute(gemm_max_mma, cudaFuncAttributeMaxDynamicSharedMemorySize, SMEM_DYN);

    init_keys_kernel<<<(NRL * BATCH * PADP * BATCH + 255) / 256, 256>>>();
    {
        int n = NRL * BATCH * (PADP - PATCHES) * (DIM / 8);
        zero_pad_kernel<<<(n + 255) / 256, 256>>>();
    }
    pool_norm_kernel<<<dim3(PATCHES, BATCH, NRL), 256>>>(feat);
    gemm_max_mma<<<dim3(25, NPAIRS, NRL), 256, SMEM_DYN>>>();
    score_kernel<<<(BATCH * PATCHES + 255) / 256, 256>>>();
    image_kernel<<<BATCH, 256>>>(out);
    bilinear_kernel<<<(BATCH * OUTH * OUTW + 255) / 256, 256>>>(out);
}

// round 4
// speedup vs baseline: 7.0773x; 1.1121x over previous
#include <cuda_runtime.h>
#include <cuda_bf16.h>
#include <cstdint>
#include <math.h>

#define L_LAYERS 4
#define BATCH    8
#define PHN      24
#define PWN      24
#define PATCHES  576
#define DIM      1024
#define NRL      12
#define NPAIRS   28
#define OUTH     336
#define OUTW     336
#define PADP     640            // 5 tiles of 128
#define TILE     128
#define KS       32             // k per slab
#define NSLAB    32             // 1024/32
#define STAGES   4
#define ROWB     80             // smem row stride bytes (64 data + 16 pad)
#define STAGEB   (2 * TILE * ROWB)   // A+B per stage = 20480
#define SMEM_DYN (STAGES * STAGEB)   // 81920

// ---------------- device scratch ----------------
__device__ __align__(16) __nv_bfloat16 g_featn[(size_t)NRL * BATCH * PADP * DIM];
__device__ unsigned g_keys[NRL * BATCH * PADP * BATCH];
__device__ float    g_scores[BATCH * PATCHES];

__device__ __forceinline__ unsigned enc_f(float x) {
    unsigned u = __float_as_uint(x);
    return (u & 0x80000000u) ? ~u : (u | 0x80000000u);
}
__device__ __forceinline__ float dec_f(unsigned k) {
    unsigned u = (k & 0x80000000u) ? (k & 0x7FFFFFFFu) : ~k;
    return __uint_as_float(u);
}

__device__ __forceinline__ uint32_t smem_u32(const void* p) {
    uint32_t a;
    asm("{ .reg .u64 t; cvta.to.shared.u64 t, %1; cvt.u32.u64 %0, t; }" : "=r"(a) : "l"(p));
    return a;
}

#define CP16(dst, src) asm volatile("cp.async.cg.shared.global [%0], [%1], 16;" :: "r"(dst), "l"(src) : "memory")
#define CP_COMMIT()    asm volatile("cp.async.commit_group;" ::: "memory")

#define LDSM_X4(r0, r1, r2, r3, a) \
    asm volatile("ldmatrix.sync.aligned.m8n8.x4.shared.b16 {%0,%1,%2,%3}, [%4];" \
        : "=r"(r0), "=r"(r1), "=r"(r2), "=r"(r3) : "r"(a))

#define MMA16816(c, a, b) \
    asm volatile("mma.sync.aligned.m16n8k16.row.col.f32.bf16.bf16.f32 " \
        "{%0,%1,%2,%3}, {%4,%5,%6,%7}, {%8,%9}, {%0,%1,%2,%3};" \
        : "+f"((c)[0]), "+f"((c)[1]), "+f"((c)[2]), "+f"((c)[3]) \
        : "r"((a)[0]), "r"((a)[1]), "r"((a)[2]), "r"((a)[3]), "r"((b)[0]), "r"((b)[1]))

// ---------------- init / pad ----------------
__global__ void init_keys_kernel() {
    int i = blockIdx.x * 256 + threadIdx.x;
    if (i < NRL * BATCH * PADP * BATCH) g_keys[i] = 0u;
}
__global__ void zero_pad_kernel() {
    int i = blockIdx.x * 256 + threadIdx.x;
    const int ROWV = DIM / 8;                          // 128 uint4 per row
    const int PER  = (PADP - PATCHES) * ROWV;          // 64*128 per slice
    if (i >= NRL * BATCH * PER) return;
    int zb = i / PER, rem = i % PER;
    int row = PATCHES + rem / ROWV, v = rem % ROWV;
    uint4* dst = (uint4*)g_featn;
    dst[((size_t)zb * PADP + row) * ROWV + v] = make_uint4(0, 0, 0, 0);
}

// ---------------- pool (all 3 radii, one 5x5 read) + normalize -> bf16 ------
// grid: (PATCHES, BATCH, L_LAYERS), block 256
__global__ void pool_norm_kernel(const float* __restrict__ feat) {
    int p = blockIdx.x, b = blockIdx.y, l = blockIdx.z;
    int ph = p / PWN, pw = p % PWN;
    int t = threadIdx.x;
    int d0 = t * 4;

    const float* base = feat + ((size_t)(l * BATCH + b) * PATCHES) * DIM;

    float4 s5 = make_float4(0.f, 0.f, 0.f, 0.f);
    float4 s3 = make_float4(0.f, 0.f, 0.f, 0.f);
    float4 s1 = make_float4(0.f, 0.f, 0.f, 0.f);

    #pragma unroll
    for (int dy = -2; dy <= 2; ++dy) {
        int y = ph + dy;
        if ((unsigned)y >= (unsigned)PHN) continue;
        #pragma unroll
        for (int dx = -2; dx <= 2; ++dx) {
            int x = pw + dx;
            if ((unsigned)x >= (unsigned)PWN) continue;
            const float4 v = *(const float4*)(base + (size_t)(y * PWN + x) * DIM + d0);
            s5.x += v.x; s5.y += v.y; s5.z += v.z; s5.w += v.w;
            if (dy >= -1 && dy <= 1 && dx >= -1 && dx <= 1) {
                s3.x += v.x; s3.y += v.y; s3.z += v.z; s3.w += v.w;
                if (dy == 0 && dx == 0) s1 = v;
            }
        }
    }
    s3.x *= (1.f/9.f);  s3.y *= (1.f/9.f);  s3.z *= (1.f/9.f);  s3.w *= (1.f/9.f);
    s5.x *= (1.f/25.f); s5.y *= (1.f/25.f); s5.z *= (1.f/25.f); s5.w *= (1.f/25.f);

    float q1 = s1.x*s1.x + s1.y*s1.y + s1.z*s1.z + s1.w*s1.w;
    float q3 = s3.x*s3.x + s3.y*s3.y + s3.z*s3.z + s3.w*s3.w;
    float q5 = s5.x*s5.x + s5.y*s5.y + s5.z*s5.z + s5.w*s5.w;
    #pragma unroll
    for (int o = 16; o > 0; o >>= 1) {
        q1 += __shfl_xor_sync(0xffffffffu, q1, o);
        q3 += __shfl_xor_sync(0xffffffffu, q3, o);
        q5 += __shfl_xor_sync(0xffffffffu, q5, o);
    }
    __shared__ float ws[3][8];
    __shared__ float rn[3];
    if ((t & 31) == 0) { ws[0][t >> 5] = q1; ws[1][t >> 5] = q3; ws[2][t >> 5] = q5; }
    __syncthreads();
    if (t < 3) {
        float x = 0.f;
        #pragma unroll
        for (int w = 0; w < 8; ++w) x += ws[t][w];
        rn[t] = rsqrtf(x);
    }
    __syncthreads();

    float4 vv[3] = { s1, s3, s5 };
    #pragma unroll
    for (int ri = 0; ri < 3; ++ri) {
        float r = rn[ri];
        __nv_bfloat162 lo = __floats2bfloat162_rn(vv[ri].x * r, vv[ri].y * r);
        __nv_bfloat162 hi = __floats2bfloat162_rn(vv[ri].z * r, vv[ri].w * r);
        uint2 pk = make_uint2(*(unsigned*)&lo, *(unsigned*)&hi);
        int z = ri * 4 + l;
        *(uint2*)(g_featn + ((size_t)(z * BATCH + b) * PADP + p) * DIM + d0) = pk;
    }
}

// ---------------- bf16 mma.sync fused GEMM + bidirectional max ----------------
__device__ __forceinline__ void load_slab(uint32_t sA, uint32_t sB,
                                          const char* gA, const char* gB, int t) {
    #pragma unroll
    for (int h = 0; h < 2; ++h) {
        int ch = t + h * 256;           // 0..511
        int r = ch >> 2, c = ch & 3;
        CP16(sA + r * ROWB + c * 16, gA + (size_t)r * (DIM * 2) + c * 16);
        CP16(sB + r * ROWB + c * 16, gB + (size_t)r * (DIM * 2) + c * 16);
    }
}

__global__ void __launch_bounds__(256) gemm_max_mma() {
    extern __shared__ __align__(16) char dsm[];
    uint32_t sbase = smem_u32(dsm);

    int t = threadIdx.x;
    int wid = t >> 5, lane = t & 31;
    int warp_m = wid & 3;               // 4 row groups of 32
    int warp_n = wid >> 2;              // 2 col groups of 64

    int tile = blockIdx.x;
    int ti = tile / 5, tj = tile % 5;
    int pair = blockIdx.y, rl = blockIdx.z;

    int b = 0, rem = pair;
    #pragma unroll
    for (int bb = 0; bb < 7; ++bb) {
        int cnt = 7 - bb;
        if (rem < cnt) { b = bb; break; }
        rem -= cnt;
    }
    int c = b + 1 + rem;

    const char* gA = (const char*)(g_featn + ((size_t)(rl * BATCH + b) * PADP + ti * TILE) * DIM);
    const char* gB = (const char*)(g_featn + ((size_t)(rl * BATCH + c) * PADP + tj * TILE) * DIM);

    float acc[2][8][4];
    #pragma unroll
    for (int mi = 0; mi < 2; ++mi)
        #pragma unroll
        for (int ni = 0; ni < 8; ++ni)
            #pragma unroll
            for (int j = 0; j < 4; ++j) acc[mi][ni][j] = 0.f;

    uint32_t aoff = (uint32_t)((warp_m * 32 + (lane & 15)) * ROWB + ((lane >> 4) * 8) * 2);
    uint32_t boff = (uint32_t)((warp_n * 64 + (lane >> 4) * 8 + (lane & 7)) * ROWB + (((lane >> 3) & 1) * 8) * 2);

    // prologue: slabs 0,1,2 into stages 0,1,2
    #pragma unroll
    for (int s = 0; s < 3; ++s) {
        load_slab(sbase + s * STAGEB, sbase + s * STAGEB + TILE * ROWB,
                  gA + (size_t)s * (KS * 2), gB + (size_t)s * (KS * 2), t);
        CP_COMMIT();
    }

    for (int kc = 0; kc < NSLAB; ++kc) {
        // wait for slab kc's load (pending groups after wait: min(2, 31-kc))
        if (kc < NSLAB - 2)      asm volatile("cp.async.wait_group 2;" ::: "memory");
        else if (kc == NSLAB - 2) asm volatile("cp.async.wait_group 1;" ::: "memory");
        else                      asm volatile("cp.async.wait_group 0;" ::: "memory");
        __syncthreads();   // single barrier per iteration

        // issue prefetch for slab kc+3 into stage (kc+3)%4.
        // Safe: that stage was last read in iteration kc-1, and every warp
        // finished iteration kc-1 before this barrier.
        if (kc + 3 < NSLAB) {
            int bufw = (kc + 3) & 3;
            load_slab(sbase + bufw * STAGEB, sbase + bufw * STAGEB + TILE * ROWB,
                      gA + (size_t)(kc + 3) * (KS * 2), gB + (size_t)(kc + 3) * (KS * 2), t);
            CP_COMMIT();
        }

        int buf = kc & 3;
        uint32_t Ab = sbase + buf * STAGEB;
        uint32_t Bb = Ab + TILE * ROWB;

        #pragma unroll
        for (int ks = 0; ks < 2; ++ks) {
            uint32_t afr[2][4];
            #pragma unroll
            for (int mi = 0; mi < 2; ++mi)
                LDSM_X4(afr[mi][0], afr[mi][1], afr[mi][2], afr[mi][3],
                        Ab + aoff + mi * 16 * ROWB + ks * 32);
            uint32_t bfr[8][2];
            #pragma unroll
            for (int np = 0; np < 4; ++np)
                LDSM_X4(bfr[np * 2][0], bfr[np * 2][1], bfr[np * 2 + 1][0], bfr[np * 2 + 1][1],
                        Bb + boff + np * 16 * ROWB + ks * 32);
            #pragma unroll
            for (int mi = 0; mi < 2; ++mi)
                #pragma unroll
                for (int ni = 0; ni < 8; ++ni)
                    MMA16816(acc[mi][ni], afr[mi], bfr[ni]);
        }
    }

    // ---------------- epilogue: bidirectional max ----------------
    // writes go to stage-0 smem; last loop iteration reads stage 3 only.
    float* rowsmem = (float*)dsm;            // [2][128]
    float* colsmem = rowsmem + 256;          // [4][128]

    #pragma unroll
    for (int mi = 0; mi < 2; ++mi) {
        float rm0 = -1e30f, rm1 = -1e30f;
        #pragma unroll
        for (int ni = 0; ni < 8; ++ni) {
            rm0 = fmaxf(rm0, fmaxf(acc[mi][ni][0], acc[mi][ni][1]));
            rm1 = fmaxf(rm1, fmaxf(acc[mi][ni][2], acc[mi][ni][3]));
        }
        #pragma unroll
        for (int o = 1; o < 4; o <<= 1) {
            rm0 = fmaxf(rm0, __shfl_xor_sync(0xffffffffu, rm0, o));
            rm1 = fmaxf(rm1, __shfl_xor_sync(0xffffffffu, rm1, o));
        }
        if ((lane & 3) == 0) {
            int lr = warp_m * 32 + mi * 16 + (lane >> 2);
            rowsmem[warp_n * 128 + lr]     = rm0;
            rowsmem[warp_n * 128 + lr + 8] = rm1;
        }
    }

    #pragma unroll
    for (int ni = 0; ni < 8; ++ni) {
        float cm0 = fmaxf(fmaxf(acc[0][ni][0], acc[0][ni][2]), fmaxf(acc[1][ni][0], acc[1][ni][2]));
        float cm1 = fmaxf(fmaxf(acc[0][ni][1], acc[0][ni][3]), fmaxf(acc[1][ni][1], acc[1][ni][3]));
        #pragma unroll
        for (int o = 4; o < 32; o <<= 1) {
            cm0 = fmaxf(cm0, __shfl_xor_sync(0xffffffffu, cm0, o));
            cm1 = fmaxf(cm1, __shfl_xor_sync(0xffffffffu, cm1, o));
        }
        if (lane < 4) {
            int lc = warp_n * 64 + ni * 8 + lane * 2;
            colsmem[warp_m * 128 + lc]     = cm0;
            colsmem[warp_m * 128 + lc + 1] = cm1;
        }
    }
    __syncthreads();

    if (t < 128) {
        float m = fmaxf(rowsmem[t], rowsmem[128 + t]);
        int p = ti * TILE + t;
        unsigned* dst = &g_keys[((size_t)(rl * BATCH + b) * PADP + p) * BATCH + c];
        atomicMax(dst, enc_f(m));
    } else {
        int col = t - 128;
        float m = fmaxf(fmaxf(colsmem[col], colsmem[128 + col]),
                        fmaxf(colsmem[256 + col], colsmem[384 + col]));
        int q = tj * TILE + col;
        unsigned* dst = &g_keys[((size_t)(rl * BATCH + c) * PADP + q) * BATCH + b];
        atomicMax(dst, enc_f(m));
    }
}

// ---------------- score / image / bilinear ----------------
__global__ void score_kernel() {
    int idx = blockIdx.x * 256 + threadIdx.x;
    if (idx >= BATCH * PATCHES) return;
    int b = idx / PATCHES;
    int p = idx % PATCHES;

    float sum = 0.f;
    #pragma unroll
    for (int rl = 0; rl < NRL; ++rl) {
        const unsigned* k = &g_keys[((size_t)(rl * BATCH + b) * PADP + p) * BATCH];
        float d1 = 1e30f, d2 = 1e30f;
        #pragma unroll
        for (int cc = 0; cc < BATCH; ++cc) {
            if (cc == b) continue;
            float dot = dec_f(k[cc]);
            float d = sqrtf(fmaxf(2.0f - 2.0f * dot, 0.0f));
            if (d < d1) { d2 = d1; d1 = d; }
            else if (d < d2) { d2 = d; }
        }
        sum += 0.5f * (d1 + d2);
    }
    g_scores[idx] = sum * (1.0f / 12.0f);
}

__global__ void image_kernel(float* __restrict__ out) {
    int b = blockIdx.x;
    int t = threadIdx.x;
    float m = -1e30f;
    for (int p = t; p < PATCHES; p += 256) m = fmaxf(m, g_scores[b * PATCHES + p]);
    #pragma unroll
    for (int o = 16; o > 0; o >>= 1) m = fmaxf(m, __shfl_xor_sync(0xffffffffu, m, o));
    __shared__ float ws[8];
    if ((t & 31) == 0) ws[t >> 5] = m;
    __syncthreads();
    if (t == 0) {
        float mm = ws[0];
        #pragma unroll
        for (int w = 1; w < 8; ++w) mm = fmaxf(mm, ws[w]);
        out[b] = mm;
    }
}

__global__ void bilinear_kernel(float* __restrict__ out) {
    int idx = blockIdx.x * 256 + threadIdx.x;
    if (idx >= BATCH * OUTH * OUTW) return;
    int b = idx / (OUTH * OUTW);
    int rr = idx % (OUTH * OUTW);
    int y = rr / OUTW, x = rr % OUTW;

    const float sc = 23.0f / 335.0f;
    float fy = (float)y * sc;
    float fx = (float)x * sc;
    int y0 = (int)floorf(fy); int y1 = min(y0 + 1, PHN - 1);
    int x0 = (int)floorf(fx); int x1 = min(x0 + 1, PWN - 1);
    float wy = fy - (float)y0;
    float wx = fx - (float)x0;

    const float* s = g_scores + b * PATCHES;
    float f00 = s[y0 * PWN + x0];
    float f01 = s[y0 * PWN + x1];
    float f10 = s[y1 * PWN + x0];
    float f11 = s[y1 * PWN + x1];

    out[BATCH + idx] = f00 * (1.f - wy) * (1.f - wx) + f01 * (1.f - wy) * wx
                     + f10 * wy * (1.f - wx)         + f11 * wy * wx;
}

// ---------------- launch ----------------
extern "C" void kernel_launch(void* const* d_in, const int* in_sizes, int n_in,
                              void* d_out, int out_size) {
    const float* feat = (const float*)d_in[0];
    float* out = (float*)d_out;

    cudaFuncSetAttribute(gemm_max_mma, cudaFuncAttributeMaxDynamicSharedMemorySize, SMEM_DYN);

    init_keys_kernel<<<(NRL * BATCH * PADP * BATCH + 255) / 256, 256>>>();
    {
        int n = NRL * BATCH * (PADP - PATCHES) * (DIM / 8);
        zero_pad_kernel<<<(n + 255) / 256, 256>>>();
    }
    pool_norm_kernel<<<dim3(PATCHES, BATCH, L_LAYERS), 256>>>(feat);
    gemm_max_mma<<<dim3(25, NPAIRS, NRL), 256, SMEM_DYN>>>();
    score_kernel<<<(BATCH * PATCHES + 255) / 256, 256>>>();
    image_kernel<<<BATCH, 256>>>(out);
    bilinear_kernel<<<(BATCH * OUTH * OUTW + 255) / 256, 256>>>(out);
}